// round 6
// baseline (speedup 1.0000x reference)
#include <cuda_runtime.h>
#include <math.h>

// Problem constants
static constexpr int Bz   = 32;
static constexpr int INC  = 64;
static constexpr int HIDN = 128;
static constexpr int Gg   = 384;
static constexpr int RR   = 63;
static constexpr int CELLS = RR * RR; // 3969

// Scratch (allocation-free: __device__ globals)
__device__ float g_gx [(size_t)4 * CELLS * Bz * Gg];    // gx = x@Wx + b   [d][p][q][b][g]
__device__ float g_h  [(size_t)4 * CELLS * Bz * HIDN];  // hidden states   [d][p][q][b][k]
__device__ float g_Whi[(size_t)4 * 256 * Gg];           // trunc13([Wh;Wh2])  [d][k'][g]
__device__ float g_Wlo[(size_t)4 * 256 * Gg];           // residual           [d][k'][g]

// ---------------------------------------------------------------------------
__device__ __forceinline__ unsigned smem_u32(const void* p) {
    return (unsigned)__cvta_generic_to_shared(p);
}
#define CPA16(dst, src) asm volatile("cp.async.cg.shared.global [%0], [%1], 16;" :: "r"(dst), "l"(src))
#define CPC()  asm volatile("cp.async.commit_group;")
#define CPW1() asm volatile("cp.async.wait_group 1;")
#define CPW0() asm volatile("cp.async.wait_group 0;")

#define MMA_TF32(D, a0, a1, a2, a3, bb0, bb1)                                   \
    asm volatile("mma.sync.aligned.m16n8k8.row.col.f32.tf32.tf32.f32 "          \
                 "{%0,%1,%2,%3}, {%4,%5,%6,%7}, {%8,%9}, {%0,%1,%2,%3};"        \
                 : "+f"(D[0]), "+f"(D[1]), "+f"(D[2]), "+f"(D[3])               \
                 : "r"(a0), "r"(a1), "r"(a2), "r"(a3), "r"(bb0), "r"(bb1))

__device__ __forceinline__ float sigf(float x)  { return 1.f / (1.f + __expf(-x)); }
__device__ __forceinline__ float tanhf_fast(float x) {
    float e = __expf(2.f * x);
    return (e - 1.f) / (e + 1.f);
}
__device__ __forceinline__ float trunc_tf32(float x) {
    return __uint_as_float(__float_as_uint(x) & 0xFFFFE000u);
}

// ---------------------------------------------------------------------------
__global__ void fill_ones_kernel(float4* out, int n4) {
    int i = blockIdx.x * 256 + threadIdx.x;
    if (i < n4) out[i] = make_float4(1.f, 1.f, 1.f, 1.f);
}

// ---------------------------------------------------------------------------
// Split [Wh;Wh2] into tf32 hi/lo pair. 4*256*384 = 393216 elems = 768 x 512.
__global__ void wsplit_kernel(const float* __restrict__ Wh,
                              const float* __restrict__ Wh2) {
    int i = blockIdx.x * 512 + threadIdx.x;
    int d = i / (256 * Gg);
    int r = (i / Gg) % 256;
    int g = i % Gg;
    float w = (r < 128) ? Wh [(size_t)d * 128 * Gg + (size_t)r * Gg + g]
                        : Wh2[(size_t)d * 128 * Gg + (size_t)(r - 128) * Gg + g];
    float hi = trunc_tf32(w);
    g_Whi[i] = hi;
    g_Wlo[i] = w - hi;
}

// ---------------------------------------------------------------------------
// gx precompute (fp32 FFMA, unchanged from R4 — fully parallel, not critical path)
static constexpr int GX_SMEM = (32 * 68 + 2 * 16 * Gg) * 4;

__global__ void __launch_bounds__(256) gx_kernel(const float* __restrict__ x,
                                                 const float* __restrict__ Wx,
                                                 const float* __restrict__ bias) {
    extern __shared__ float sm[];
    float* Xs  = sm;
    float* Wsb = sm + 32 * 68;

    const int cellpq = blockIdx.x;
    const int d      = blockIdx.y;
    const int p = cellpq / RR, q = cellpq % RR;
    const int ix = (d & 1) ? (62 - p) : p;
    const int jx = (d & 2) ? (62 - q) : q;
    const int t = threadIdx.x;
    const int tx = t & 15, ty = t >> 4;
    const int b0 = ty * 2;
    const float* Wd = Wx + (size_t)d * INC * Gg;

    auto stageW = [&](int kb, int buf) {
        float* W = Wsb + buf * (16 * Gg);
        for (int f = t; f < 16 * 96; f += 256) {
            int kk = f / 96, x16 = f % 96;
            CPA16(smem_u32(W + kk * Gg + x16 * 4),
                  Wd + (size_t)(kb * 16 + kk) * Gg + x16 * 4);
        }
    };
    stageW(0, 0); CPC();
    stageW(1, 1); CPC();

    for (int m = t; m < Bz * INC; m += 256) {
        int b_ = m >> 6, c = m & 63;
        Xs[b_ * 68 + c] = x[((size_t)(b_ * INC + c) << 12) + (ix << 6) + jx];
    }

    float acc[6][4][2];
    const float* bb = bias + d * Gg;
#pragma unroll
    for (int c = 0; c < 6; c++) {
        float4 v = *(const float4*)(bb + c * 64 + tx * 4);
        acc[c][0][0] = v.x; acc[c][0][1] = v.x;
        acc[c][1][0] = v.y; acc[c][1][1] = v.y;
        acc[c][2][0] = v.z; acc[c][2][1] = v.z;
        acc[c][3][0] = v.w; acc[c][3][1] = v.w;
    }

#pragma unroll 1
    for (int kb = 0; kb < 4; kb++) {
        if (kb < 3) { CPW1(); } else { CPW0(); }
        __syncthreads();
        const float* W = Wsb + (kb & 1) * (16 * Gg);
        const float* Arow = Xs + b0 * 68 + kb * 16;
#pragma unroll 8
        for (int kk = 0; kk < 16; kk++) {
            float a0 = Arow[kk];
            float a1 = Arow[68 + kk];
            const float* wr = W + kk * Gg + tx * 4;
#pragma unroll
            for (int c = 0; c < 6; c++) {
                float4 w = *(const float4*)(wr + c * 64);
                acc[c][0][0] += a0 * w.x; acc[c][0][1] += a1 * w.x;
                acc[c][1][0] += a0 * w.y; acc[c][1][1] += a1 * w.y;
                acc[c][2][0] += a0 * w.z; acc[c][2][1] += a1 * w.z;
                acc[c][3][0] += a0 * w.w; acc[c][3][1] += a1 * w.w;
            }
        }
        __syncthreads();
        if (kb < 2) { stageW(kb + 2, kb & 1); CPC(); }
    }

    float* gp = g_gx + ((size_t)(d * CELLS + cellpq) * Bz + b0) * Gg;
#pragma unroll
    for (int c = 0; c < 6; c++) {
#pragma unroll
        for (int b2 = 0; b2 < 2; b2++) {
            *(float4*)(gp + (size_t)b2 * Gg + c * 64 + tx * 4) =
                make_float4(acc[c][0][b2], acc[c][1][b2], acc[c][2][b2], acc[c][3][b2]);
        }
    }
}

// ---------------------------------------------------------------------------
// scan (3xTF32 mma.sync): one CTA = (direction, pair of diagonal cells).
// D[64][384] = A[64][256] @ W[256][384] computed as hi*hi + hi*lo + lo*hi
// over a fused K'=768 loop. 16 warps; warp w owns gate-triple n-tiles
// {w*8, 128+w*8, 256+w*8} x 4 m-tiles. All-register GRU epilogue.
static constexpr int PAD_A = 260;   // words per A row (conflict-free: 260 % 32 = 4)
static constexpr int PAD_W = 392;   // words per W row (conflict-free: 392 % 32 = 8)
static constexpr int SCAN_SMEM = (2 * 64 * PAD_A + 2 * 16 * PAD_W) * 4;  // 183296 B

__global__ void __launch_bounds__(512, 1) scan_mma_kernel(float* __restrict__ out,
                                                          int s, int qlo, int qhi) {
    extern __shared__ float sm[];
    float* Ahi = sm;                        // [64][260]
    float* Alo = sm + 64 * PAD_A;           // [64][260]
    float* Wsm = sm + 2 * 64 * PAD_A;       // [2][16][392]

    const int d  = blockIdx.y;
    const int q0 = qlo + 2 * blockIdx.x;
    const int q1 = q0 + 1;
    const bool c1ok = (q1 <= qhi);
    const int p0 = s - q0;
    const int p1 = s - q1;
    const size_t cell0 = (size_t)d * CELLS + (size_t)p0 * RR + q0;
    const size_t cell1 = (size_t)d * CELLS + (size_t)p1 * RR + q1;

    const int t = threadIdx.x;
    const int w = t >> 5, lane = t & 31;
    const int gi = lane >> 2, ci = lane & 3;
    const int n0 = w * 8;

    // ---- W chunk staging (16 k-rows x 384) ----
    auto stageW = [&](int cb, int buf) {
        const int seg = cb >> 4;                 // 0: hi*hi  1: hi*lo  2: lo*hi
        const int kb  = (cb & 15) * 16;
        const float* base = ((seg == 1) ? g_Wlo : g_Whi)
                            + (size_t)d * 256 * Gg + (size_t)kb * Gg;
        float* Wdst = Wsm + buf * (16 * PAD_W);
        for (int f = t; f < 1536; f += 512) {
            int r = f / 96, c16 = f % 96;
            CPA16(smem_u32(Wdst + r * PAD_W + c16 * 4), base + r * Gg + c16 * 4);
        }
    };
    stageW(0, 0); CPC();
    stageW(1, 1); CPC();

    // ---- A staging: rows 0-31 cell0, 32-63 cell1; cols [0,128)=h_up, [128,256)=h_left ----
    {
        const float* hu0 = (p0 > 0) ? g_h + (cell0 - RR) * (Bz * HIDN) : nullptr;
        const float* hl0 = (q0 > 0) ? g_h + (cell0 - 1)  * (Bz * HIDN) : nullptr;
        const float* hu1 = (c1ok && p1 > 0) ? g_h + (cell1 - RR) * (Bz * HIDN) : nullptr;
        const float* hl1 = (c1ok && q1 > 0) ? g_h + (cell1 - 1)  * (Bz * HIDN) : nullptr;
        for (int f = t; f < 4096; f += 512) {
            int row = f >> 6;
            int col = (f & 63) * 4;
            const float* src = nullptr;
            if (row < 32) {
                src = (col < 128) ? (hu0 ? hu0 + row * 128 + col : nullptr)
                                  : (hl0 ? hl0 + row * 128 + (col - 128) : nullptr);
            } else {
                src = (col < 128) ? (hu1 ? hu1 + (row - 32) * 128 + col : nullptr)
                                  : (hl1 ? hl1 + (row - 32) * 128 + (col - 128) : nullptr);
            }
            float4 v = src ? *(const float4*)src : make_float4(0.f, 0.f, 0.f, 0.f);
            float4 hi, lo;
            hi.x = trunc_tf32(v.x); lo.x = v.x - hi.x;
            hi.y = trunc_tf32(v.y); lo.y = v.y - hi.y;
            hi.z = trunc_tf32(v.z); lo.z = v.z - hi.z;
            hi.w = trunc_tf32(v.w); lo.w = v.w - hi.w;
            *(float4*)(Ahi + row * PAD_A + col) = hi;
            *(float4*)(Alo + row * PAD_A + col) = lo;
        }
    }

    float acc[4][3][4];
#pragma unroll
    for (int mt = 0; mt < 4; mt++)
#pragma unroll
        for (int gt = 0; gt < 3; gt++)
#pragma unroll
            for (int j = 0; j < 4; j++) acc[mt][gt][j] = 0.f;

    // ---- main K' loop: 48 chunks of 16 k-rows (3 segments x 16) ----
#pragma unroll 1
    for (int cb = 0; cb < 48; cb++) {
        if (cb < 47) { CPW1(); } else { CPW0(); }
        __syncthreads();
        const int seg = cb >> 4;
        const float* Aseg = (seg == 2) ? Alo : Ahi;
        const int kb = (cb & 15) * 16;
        const float* Wb = Wsm + (cb & 1) * (16 * PAD_W);

#pragma unroll
        for (int ks = 0; ks < 2; ks++) {
            const int kr = ks * 8;
            const int kc = kb + kr;
            unsigned b0[3], b1[3];
#pragma unroll
            for (int gt = 0; gt < 3; gt++) {
                b0[gt] = __float_as_uint(Wb[(kr + ci) * PAD_W + gt * 128 + n0 + gi]);
                b1[gt] = __float_as_uint(Wb[(kr + ci + 4) * PAD_W + gt * 128 + n0 + gi]);
            }
#pragma unroll
            for (int mt = 0; mt < 4; mt++) {
                const float* Ab = Aseg + (mt * 16 + gi) * PAD_A + kc + ci;
                unsigned a0 = __float_as_uint(Ab[0]);
                unsigned a1 = __float_as_uint(Ab[8 * PAD_A]);
                unsigned a2 = __float_as_uint(Ab[4]);
                unsigned a3 = __float_as_uint(Ab[8 * PAD_A + 4]);
#pragma unroll
                for (int gt = 0; gt < 3; gt++) {
                    MMA_TF32(acc[mt][gt], a0, a1, a2, a3, b0[gt], b1[gt]);
                }
            }
        }
        __syncthreads();
        if (cb < 46) { stageW(cb + 2, cb & 1); CPC(); }
    }

    // ---- GRU epilogue (all register; gx read from global, h from smem) ----
#pragma unroll
    for (int mt = 0; mt < 4; mt++) {
#pragma unroll
        for (int half = 0; half < 2; half++) {
            const int r = mt * 16 + gi + half * 8;
            const int cIdx = r >> 5;
            if (cIdx == 1 && !c1ok) continue;
            const size_t cell = cIdx ? cell1 : cell0;
            const int p = cIdx ? p1 : p0;
            const int q = cIdx ? q1 : q0;
            const int b = r & 31;
            const float* gxc = g_gx + (cell * Bz + b) * Gg;
            float* hdst = g_h + cell * (Bz * HIDN);
            const int oi = (d & 1) ? (63 - p) : p;
            const int oj = (d & 2) ? (63 - q) : q;
#pragma unroll
            for (int c = 0; c < 2; c++) {
                const int k = n0 + 2 * ci + c;
                float ar = acc[mt][0][half * 2 + c];
                float az = acc[mt][1][half * 2 + c];
                float an = acc[mt][2][half * 2 + c];
                float rr_ = sigf(ar + gxc[k]);
                float zz  = sigf(az + gxc[128 + k]);
                float nn  = tanhf_fast(gxc[256 + k] + rr_ * an);
                float hu  = Ahi[r * PAD_A + k]       + Alo[r * PAD_A + k];
                float hl  = Ahi[r * PAD_A + 128 + k] + Alo[r * PAD_A + 128 + k];
                float h   = (1.f - zz) * nn + zz * 0.5f * (hu + hl);
                hdst[b * 128 + k] = h;
                out[((size_t)(b * 128 + k) * 4 + d) * 4096 + (size_t)oi * 64 + oj] = h;
            }
        }
    }
}

// ---------------------------------------------------------------------------
extern "C" void kernel_launch(void* const* d_in, const int* in_sizes, int n_in,
                              void* d_out, int out_size) {
    const float* x    = (const float*)d_in[0];
    const float* Wx   = (const float*)d_in[1];
    const float* Wh   = (const float*)d_in[2];
    const float* Wh2  = (const float*)d_in[3];
    const float* bias = (const float*)d_in[4];
    float* out = (float*)d_out;

    cudaFuncSetAttribute(scan_mma_kernel, cudaFuncAttributeMaxDynamicSharedMemorySize, SCAN_SMEM);
    cudaFuncSetAttribute(gx_kernel,       cudaFuncAttributeMaxDynamicSharedMemorySize, GX_SMEM);

    // 1) output border fill + weight split (independent prep)
    int n4 = out_size / 4;
    fill_ones_kernel<<<(n4 + 255) / 256, 256>>>((float4*)d_out, n4);
    wsplit_kernel<<<768, 512>>>(Wh, Wh2);

    // 2) gx precompute
    {
        dim3 grid(CELLS, 4);
        gx_kernel<<<grid, 256, GX_SMEM>>>(x, Wx, bias);
    }

    // 3) wavefront: one launch per anti-diagonal, 2 cells per CTA
    for (int s = 0; s < 2 * RR - 1; s++) {
        int qlo = (s - (RR - 1) > 0) ? (s - (RR - 1)) : 0;
        int qhi = (s < RR - 1) ? s : (RR - 1);
        int nq = qhi - qlo + 1;
        int npairs = (nq + 1) / 2;
        dim3 grid(npairs, 4);
        scan_mma_kernel<<<grid, 512, SCAN_SMEM>>>(out, s, qlo, qhi);
    }
}

// round 7
// speedup vs baseline: 1.5000x; 1.5000x over previous
#include <cuda_runtime.h>
#include <cuda_bf16.h>
#include <math.h>

// Problem constants
static constexpr int Bz   = 32;
static constexpr int INC  = 64;
static constexpr int HIDN = 128;
static constexpr int Gg   = 384;
static constexpr int RR   = 63;
static constexpr int CELLS = RR * RR; // 3969
static constexpr int NCTAS = 144;     // 4 dirs x 4 k-quarters x 9 CTAs

// Scratch (allocation-free: __device__ globals)
__device__ float g_gx [(size_t)4 * CELLS * Bz * Gg];    // gx = x@Wx + b   [d][p][q][b][g]
__device__ float g_h  [(size_t)4 * CELLS * Bz * HIDN];  // hidden states   [d][p][q][b][k]
__device__ float g_Whi[(size_t)4 * 256 * Gg];           // trunc13([Wh;Wh2])  [d][k'][g]
__device__ float g_Wlo[(size_t)4 * 256 * Gg];           // residual           [d][k'][g]
__device__ int            g_bar_count;
__device__ volatile int   g_bar_gen;

// ---------------------------------------------------------------------------
__device__ __forceinline__ unsigned smem_u32(const void* p) {
    return (unsigned)__cvta_generic_to_shared(p);
}
#define CPA16(dst, src) asm volatile("cp.async.cg.shared.global [%0], [%1], 16;" :: "r"(dst), "l"(src))
#define CPC()  asm volatile("cp.async.commit_group;")
#define CPW0() asm volatile("cp.async.wait_group 0;")
#define CPW1() asm volatile("cp.async.wait_group 1;")

#define MMA_TF32(D, a0, a1, a2, a3, bb0, bb1)                                   \
    asm volatile("mma.sync.aligned.m16n8k8.row.col.f32.tf32.tf32.f32 "          \
                 "{%0,%1,%2,%3}, {%4,%5,%6,%7}, {%8,%9}, {%0,%1,%2,%3};"        \
                 : "+f"(D[0]), "+f"(D[1]), "+f"(D[2]), "+f"(D[3])               \
                 : "r"(a0), "r"(a1), "r"(a2), "r"(a3), "r"(bb0), "r"(bb1))

__device__ __forceinline__ float sigf(float x)  { return 1.f / (1.f + __expf(-x)); }
__device__ __forceinline__ float tanhf_fast(float x) {
    float e = __expf(2.f * x);
    return (e - 1.f) / (e + 1.f);
}
__device__ __forceinline__ float trunc_tf32(float x) {
    return __uint_as_float(__float_as_uint(x) & 0xFFFFE000u);
}

// ---------------------------------------------------------------------------
__global__ void fill_ones_kernel(float4* out, int n4) {
    int i = blockIdx.x * 256 + threadIdx.x;
    if (i < n4) out[i] = make_float4(1.f, 1.f, 1.f, 1.f);
}

__global__ void reset_kernel() {
    g_bar_count = 0;
    g_bar_gen   = 0;
}

// ---------------------------------------------------------------------------
// Split [Wh;Wh2] into tf32 hi/lo pair. 4*256*384 elems = 768 x 512.
__global__ void wsplit_kernel(const float* __restrict__ Wh,
                              const float* __restrict__ Wh2) {
    int i = blockIdx.x * 512 + threadIdx.x;
    int d = i / (256 * Gg);
    int r = (i / Gg) % 256;
    int g = i % Gg;
    float w = (r < 128) ? Wh [(size_t)d * 128 * Gg + (size_t)r * Gg + g]
                        : Wh2[(size_t)d * 128 * Gg + (size_t)(r - 128) * Gg + g];
    float hi = trunc_tf32(w);
    g_Whi[i] = hi;
    g_Wlo[i] = w - hi;
}

// ---------------------------------------------------------------------------
// gx precompute (fp32 FFMA — fully parallel, off the critical path)
static constexpr int GX_SMEM = (32 * 68 + 2 * 16 * Gg) * 4;

__global__ void __launch_bounds__(256) gx_kernel(const float* __restrict__ x,
                                                 const float* __restrict__ Wx,
                                                 const float* __restrict__ bias) {
    extern __shared__ float sm[];
    float* Xs  = sm;
    float* Wsb = sm + 32 * 68;

    const int cellpq = blockIdx.x;
    const int d      = blockIdx.y;
    const int p = cellpq / RR, q = cellpq % RR;
    const int ix = (d & 1) ? (62 - p) : p;
    const int jx = (d & 2) ? (62 - q) : q;
    const int t = threadIdx.x;
    const int tx = t & 15, ty = t >> 4;
    const int b0 = ty * 2;
    const float* Wd = Wx + (size_t)d * INC * Gg;

    auto stageW = [&](int kb, int buf) {
        float* W = Wsb + buf * (16 * Gg);
        for (int f = t; f < 16 * 96; f += 256) {
            int kk = f / 96, x16 = f % 96;
            CPA16(smem_u32(W + kk * Gg + x16 * 4),
                  Wd + (size_t)(kb * 16 + kk) * Gg + x16 * 4);
        }
    };
    stageW(0, 0); CPC();
    stageW(1, 1); CPC();

    for (int m = t; m < Bz * INC; m += 256) {
        int b_ = m >> 6, c = m & 63;
        Xs[b_ * 68 + c] = x[((size_t)(b_ * INC + c) << 12) + (ix << 6) + jx];
    }

    float acc[6][4][2];
    const float* bb = bias + d * Gg;
#pragma unroll
    for (int c = 0; c < 6; c++) {
        float4 v = *(const float4*)(bb + c * 64 + tx * 4);
        acc[c][0][0] = v.x; acc[c][0][1] = v.x;
        acc[c][1][0] = v.y; acc[c][1][1] = v.y;
        acc[c][2][0] = v.z; acc[c][2][1] = v.z;
        acc[c][3][0] = v.w; acc[c][3][1] = v.w;
    }

#pragma unroll 1
    for (int kb = 0; kb < 4; kb++) {
        if (kb < 3) { CPW1(); } else { CPW0(); }
        __syncthreads();
        const float* W = Wsb + (kb & 1) * (16 * Gg);
        const float* Arow = Xs + b0 * 68 + kb * 16;
#pragma unroll 8
        for (int kk = 0; kk < 16; kk++) {
            float a0 = Arow[kk];
            float a1 = Arow[68 + kk];
            const float* wr = W + kk * Gg + tx * 4;
#pragma unroll
            for (int c = 0; c < 6; c++) {
                float4 w = *(const float4*)(wr + c * 64);
                acc[c][0][0] += a0 * w.x; acc[c][0][1] += a1 * w.x;
                acc[c][1][0] += a0 * w.y; acc[c][1][1] += a1 * w.y;
                acc[c][2][0] += a0 * w.z; acc[c][2][1] += a1 * w.z;
                acc[c][3][0] += a0 * w.w; acc[c][3][1] += a1 * w.w;
            }
        }
        __syncthreads();
        if (kb < 2) { stageW(kb + 2, kb & 1); CPC(); }
    }

    float* gp = g_gx + ((size_t)(d * CELLS + cellpq) * Bz + b0) * Gg;
#pragma unroll
    for (int c = 0; c < 6; c++) {
#pragma unroll
        for (int b2 = 0; b2 < 2; b2++) {
            *(float4*)(gp + (size_t)b2 * Gg + c * 64 + tx * 4) =
                make_float4(acc[c][0][b2], acc[c][1][b2], acc[c][2][b2], acc[c][3][b2]);
        }
    }
}

// ---------------------------------------------------------------------------
// Persistent wavefront scan. CTA = (d, k-quarter, j). Weights stationary in
// SMEM (Whi fp32 + Wlo bf16, rows padded to 104 words -> conflict-free).
// Per step: process cell-pairs q0 = qlo + 2*(j + 9t) (M=64 rows = 2 cells),
// 3xTF32 mma.sync against the resident 256x96 weight tile, all-register GRU
// epilogue, then software grid barrier.
static constexpr int PAD_W2 = 104;                    // 96 cols + 8 pad
static constexpr int PAD_A2 = 260;                    // 256 cols + 4 pad
static constexpr int PERSIST_SMEM =
    256 * PAD_W2 * 4 + 256 * PAD_W2 * 2 + 64 * PAD_A2 * 4;   // 226304 B

__device__ __forceinline__ void grid_barrier(int gen) {
    __syncthreads();
    if (threadIdx.x == 0) {
        __threadfence();
        if (atomicAdd(&g_bar_count, 1) == NCTAS - 1) {
            g_bar_count = 0;
            __threadfence();
            g_bar_gen = gen;
        } else {
            while (g_bar_gen < gen) { __nanosleep(64); }
            __threadfence();
        }
    }
    __syncthreads();
}

__global__ void __launch_bounds__(256, 1) scan_persist_kernel(float* __restrict__ out) {
    extern __shared__ float sm[];
    float* Wh_s = sm;                                            // [256][104] fp32
    __nv_bfloat16* Wl_s = (__nv_bfloat16*)(sm + 256 * PAD_W2);   // [256][104] bf16
    float* A = sm + 256 * PAD_W2 + 256 * PAD_W2 / 2;             // [64][260]  fp32

    const int cta = blockIdx.x;
    const int d  = cta / 36;
    const int kq = (cta / 9) % 4;
    const int j  = cta % 9;
    const int t  = threadIdx.x;
    const int w = t >> 5, lane = t & 31;
    const int gi = lane >> 2, ci = lane & 3;
    const int mp = w >> 2, ng = w & 3;   // mp: cell within pair; ng: koff octet

    // ---- one-time weight staging: cols c = gate*32 + koff ----
    for (int idx = t; idx < 256 * 96; idx += 256) {
        int k = idx / 96, c = idx % 96;
        int gate = c >> 5, koff = c & 31;
        size_t gsrc = ((size_t)d * 256 + k) * Gg + gate * 128 + kq * 32 + koff;
        Wh_s[k * PAD_W2 + c] = g_Whi[gsrc];
        Wl_s[k * PAD_W2 + c] = __float2bfloat16(g_Wlo[gsrc]);
    }
    __syncthreads();

    for (int s = 0; s < 2 * RR - 1; s++) {
        const int qlo = (s - (RR - 1) > 0) ? (s - (RR - 1)) : 0;
        const int qhi = (s < RR - 1) ? s : (RR - 1);
        const int npairs = (qhi - qlo + 2) >> 1;

        for (int pi = j; pi < npairs; pi += 9) {
            const int q0 = qlo + 2 * pi;
            const int q1 = q0 + 1;
            const bool c1ok = (q1 <= qhi);
            const int p0 = s - q0;
            const int p1 = s - q1;
            const size_t cell0 = (size_t)d * CELLS + (size_t)p0 * RR + q0;
            const size_t cell1 = (size_t)d * CELLS + (size_t)p1 * RR + q1;

            // ---- stage A: rows 0-31 cell0, 32-63 cell1; cols [0,128)=h_up,
            //      [128,256)=h_left. cp.async.cg (L1-bypass: cross-CTA h).
            {
                const float* hu0 = (p0 > 0) ? g_h + (cell0 - RR) * (Bz * HIDN) : nullptr;
                const float* hl0 = (q0 > 0) ? g_h + (cell0 - 1)  * (Bz * HIDN) : nullptr;
                const float* hu1 = (c1ok && p1 > 0) ? g_h + (cell1 - RR) * (Bz * HIDN) : nullptr;
                const float* hl1 = (c1ok && q1 > 0) ? g_h + (cell1 - 1)  * (Bz * HIDN) : nullptr;
                for (int f = t; f < 4096; f += 256) {
                    int row = f >> 6;
                    int col = (f & 63) * 4;
                    const float* src;
                    if (row < 32)
                        src = (col < 128) ? (hu0 ? hu0 + row * 128 + col : nullptr)
                                          : (hl0 ? hl0 + row * 128 + (col - 128) : nullptr);
                    else
                        src = (col < 128) ? (hu1 ? hu1 + (row - 32) * 128 + col : nullptr)
                                          : (hl1 ? hl1 + (row - 32) * 128 + (col - 128) : nullptr);
                    float* dst = A + row * PAD_A2 + col;
                    if (src) { CPA16(smem_u32(dst), src); }
                    else     { *(float4*)dst = make_float4(0.f, 0.f, 0.f, 0.f); }
                }
                CPC(); CPW0();
                __syncthreads();
            }

            // ---- 3xTF32 MMA mainloop over K=256 (32 k-steps of 8) ----
            float acc[2][3][4];
#pragma unroll
            for (int mt = 0; mt < 2; mt++)
#pragma unroll
                for (int g = 0; g < 3; g++)
#pragma unroll
                    for (int v = 0; v < 4; v++) acc[mt][g][v] = 0.f;

            const int cb0 = ng * 8 + gi;       // B col within tile (per gate)
            const float* Arow0 = A + (mp * 32 + gi) * PAD_A2 + ci;

#pragma unroll 4
            for (int k8 = 0; k8 < 32; k8++) {
                const int kr = k8 * 8;
                unsigned bh0[3], bh1[3], bl0[3], bl1[3];
#pragma unroll
                for (int g = 0; g < 3; g++) {
                    const int c = g * 32 + cb0;
                    bh0[g] = __float_as_uint(Wh_s[(kr + ci) * PAD_W2 + c]);
                    bh1[g] = __float_as_uint(Wh_s[(kr + ci + 4) * PAD_W2 + c]);
                    bl0[g] = __float_as_uint(__bfloat162float(Wl_s[(kr + ci) * PAD_W2 + c]));
                    bl1[g] = __float_as_uint(__bfloat162float(Wl_s[(kr + ci + 4) * PAD_W2 + c]));
                }
#pragma unroll
                for (int mt = 0; mt < 2; mt++) {
                    const float* Ab = Arow0 + mt * 16 * PAD_A2 + kr;
                    float a0 = Ab[0], a1 = Ab[8 * PAD_A2];
                    float a2 = Ab[4], a3 = Ab[8 * PAD_A2 + 4];
                    unsigned ua0 = __float_as_uint(a0), ua1 = __float_as_uint(a1);
                    unsigned ua2 = __float_as_uint(a2), ua3 = __float_as_uint(a3);
                    unsigned ul0 = __float_as_uint(a0 - trunc_tf32(a0));
                    unsigned ul1 = __float_as_uint(a1 - trunc_tf32(a1));
                    unsigned ul2 = __float_as_uint(a2 - trunc_tf32(a2));
                    unsigned ul3 = __float_as_uint(a3 - trunc_tf32(a3));
#pragma unroll
                    for (int g = 0; g < 3; g++) {
                        MMA_TF32(acc[mt][g], ua0, ua1, ua2, ua3, bh0[g], bh1[g]);  // hi*hi
                        MMA_TF32(acc[mt][g], ua0, ua1, ua2, ua3, bl0[g], bl1[g]);  // hi*lo
                        MMA_TF32(acc[mt][g], ul0, ul1, ul2, ul3, bh0[g], bh1[g]);  // lo*hi
                    }
                }
            }

            // ---- GRU epilogue (warp mp owns cell mp) ----
            if (!(mp == 1 && !c1ok)) {
                const size_t cell = mp ? cell1 : cell0;
                const int p = mp ? p1 : p0;
                const int q = mp ? q1 : q0;
                const int oi = (d & 1) ? (63 - p) : p;
                const int oj = (d & 2) ? (63 - q) : q;
                float* hdst = g_h + cell * (Bz * HIDN);
#pragma unroll
                for (int mt = 0; mt < 2; mt++) {
#pragma unroll
                    for (int half = 0; half < 2; half++) {
                        const int b = mt * 16 + gi + half * 8;   // batch row
                        const int row = mp * 32 + b;             // A row
                        const float* gxc = g_gx + (cell * Bz + b) * Gg;
#pragma unroll
                        for (int c = 0; c < 2; c++) {
                            const int k = kq * 32 + ng * 8 + 2 * ci + c;
                            float rr_ = sigf(acc[mt][0][half * 2 + c] + gxc[k]);
                            float zz  = sigf(acc[mt][1][half * 2 + c] + gxc[128 + k]);
                            float nn  = tanhf_fast(gxc[256 + k] + rr_ * acc[mt][2][half * 2 + c]);
                            float hu  = A[row * PAD_A2 + k];
                            float hl  = A[row * PAD_A2 + 128 + k];
                            float h   = (1.f - zz) * nn + zz * 0.5f * (hu + hl);
                            hdst[b * 128 + k] = h;
                            out[((size_t)(b * 128 + k) * 4 + d) * 4096 + (size_t)oi * 64 + oj] = h;
                        }
                    }
                }
            }
            __syncthreads();   // protect A before next pair overwrites it
        }

        grid_barrier(s + 1);
    }
}

// ---------------------------------------------------------------------------
extern "C" void kernel_launch(void* const* d_in, const int* in_sizes, int n_in,
                              void* d_out, int out_size) {
    const float* x    = (const float*)d_in[0];
    const float* Wx   = (const float*)d_in[1];
    const float* Wh   = (const float*)d_in[2];
    const float* Wh2  = (const float*)d_in[3];
    const float* bias = (const float*)d_in[4];
    float* out = (float*)d_out;

    cudaFuncSetAttribute(gx_kernel, cudaFuncAttributeMaxDynamicSharedMemorySize, GX_SMEM);
    cudaFuncSetAttribute(scan_persist_kernel,
                         cudaFuncAttributeMaxDynamicSharedMemorySize, PERSIST_SMEM);

    // 1) independent prep
    int n4 = out_size / 4;
    fill_ones_kernel<<<(n4 + 255) / 256, 256>>>((float4*)d_out, n4);
    wsplit_kernel<<<768, 512>>>(Wh, Wh2);
    reset_kernel<<<1, 1>>>();

    // 2) gx precompute
    {
        dim3 grid(CELLS, 4);
        gx_kernel<<<grid, 256, GX_SMEM>>>(x, Wx, bias);
    }

    // 3) persistent wavefront scan (single launch; weights SMEM-resident)
    scan_persist_kernel<<<NCTAS, 256, PERSIST_SMEM>>>(out);
}